// round 3
// baseline (speedup 1.0000x reference)
#include <cuda_runtime.h>
#include <cuda_bf16.h>

#define NN   65536
#define NE   1048576
#define NG   64
#define NPG  1024
#define CF   16
#define PAD  17

typedef unsigned long long ull;

__device__ int   g_deg[NN];
__device__ int   g_cnt[NN];
__device__ int   g_cur[NN];
__device__ int   g_rowstart[NN + 1];
__device__ float g_dis[NN];
__device__ float g_diag[NN];
__device__ int2  g_edges[NE + 64];
__device__ float g_tx[640ull * NN];
__device__ float g_ha[(size_t)NN * 64];
__device__ float g_hb[(size_t)NN * 64];

__device__ __forceinline__ ull pack2(float x, float y) {
    ull r; asm("mov.b64 %0, {%1, %2};" : "=l"(r) : "f"(x), "f"(y)); return r;
}
__device__ __forceinline__ void ffma2(ull& d, ull a, ull b) {
    asm("fma.rn.f32x2 %0, %1, %2, %0;" : "+l"(d) : "l"(a), "l"(b));
}
__device__ __forceinline__ void unpack2(ull v, float& x, float& y) {
    asm("mov.b64 {%0, %1}, %2;" : "=f"(x), "=f"(y) : "l"(v));
}

// ---------------- prep ----------------
__global__ void zero_kernel() {
    int i = blockIdx.x * blockDim.x + threadIdx.x;
    if (i < NN) { g_deg[i] = 0; g_cnt[i] = 0; g_cur[i] = 0; }
}

__global__ void deg_kernel(const int* __restrict__ ei) {
    int e = blockIdx.x * blockDim.x + threadIdx.x;
    if (e >= NE) return;
    int s = ei[e], d = ei[NE + e];
    if (s != d) { atomicAdd(&g_deg[s], 1); atomicAdd(&g_cnt[d], 1); }
}

__global__ void node_kernel(const int* __restrict__ batch,
                            const float* __restrict__ lam) {
    int n = blockIdx.x * blockDim.x + threadIdx.x;
    if (n >= NN) return;
    int dg = g_deg[n];
    g_dis[n]  = (dg > 0) ? rsqrtf((float)dg) : 0.0f;
    g_diag[n] = 2.0f / lam[batch[n]] - 1.0f;
}

__global__ void scan_kernel() {   // 1 block, 1024 threads, 64 elems each
    __shared__ int part[1024];
    int t = threadIdx.x, base = t * 64, s = 0;
    for (int j = 0; j < 64; j++) s += g_cnt[base + j];
    part[t] = s;
    __syncthreads();
    for (int off = 1; off < 1024; off <<= 1) {
        int v = (t >= off) ? part[t - off] : 0;
        __syncthreads();
        part[t] += v;
        __syncthreads();
    }
    int run = (t == 0) ? 0 : part[t - 1];
    for (int j = 0; j < 64; j++) { g_rowstart[base + j] = run; run += g_cnt[base + j]; }
    if (t == 1023) g_rowstart[NN] = run;
}

__global__ void fill_kernel(const int* __restrict__ ei,
                            const int* __restrict__ batch,
                            const float* __restrict__ lam) {
    int e = blockIdx.x * blockDim.x + threadIdx.x;
    if (e >= NE) return;
    int s = ei[e], d = ei[NE + e];
    if (s == d) return;
    float w = -2.0f * g_dis[s] * g_dis[d] / lam[batch[s]];
    int idx = g_rowstart[d] + atomicAdd(&g_cur[d], 1);
    g_edges[idx] = make_int2(s & (NPG - 1), __float_as_int(w));
}

// ---------------- Chebyshev recurrence ----------------
template<int F>
__global__ void __launch_bounds__(1024, 1)
spmv_kernel(const float* __restrict__ hin, float* __restrict__ txout) {
    extern __shared__ float sm[];
    float* buf0 = sm;
    float* buf1 = sm + NPG * PAD;

    const int g = blockIdx.y, cb = blockIdx.x * CF, t = threadIdx.x;
    const int gbase = g * NPG;

    const float* hp = hin + (size_t)gbase * F + cb;
    #pragma unroll
    for (int r = 0; r < CF; r++) {
        int i = r * 1024 + t;
        buf0[(i >> 4) * PAD + (i & 15)] = hp[(i >> 4) * F + (i & 15)];
    }
    __syncthreads();

    #pragma unroll
    for (int f = 0; f < CF; f++)
        txout[(size_t)(cb + f) * NN + gbase + t] = buf0[t * PAD + f];

    const int lane = t & 31, warp = t >> 5;
    const int half = lane >> 4, fl = lane & 15;
    float* cur = buf0; float* oth = buf1;

    for (int k = 1; k < 5; k++) {
        #pragma unroll 1
        for (int p = 0; p < 16; p++) {
            int dloc = warp * 32 + p * 2 + half;
            int node = gbase + dloc;
            int rs = g_rowstart[node];
            int deg = g_rowstart[node + 1] - rs;
            float acc = 0.0f;
            for (int i = 0; i < deg; i++) {
                int2 ed = g_edges[rs + i];
                acc += __int_as_float(ed.y) * cur[ed.x * PAD + fl];
            }
            int idx = dloc * PAD + fl;
            float lh = acc + g_diag[node] * cur[idx];
            oth[idx] = (k == 1) ? lh : 2.0f * lh - oth[idx];
        }
        __syncthreads();
        #pragma unroll
        for (int f = 0; f < CF; f++)
            txout[(size_t)(k * F + cb + f) * NN + gbase + t] = oth[t * PAD + f];
        float* tmp = cur; cur = oth; oth = tmp;
        __syncthreads();
    }
}

// ---------------- GEMM: out = relu(A^T W + b), A:[K][NN], W:[K][N] ----------------
template<int K, int N, int MT>
__global__ void __launch_bounds__(256)
gemm_kernel(const float* __restrict__ A, const float* __restrict__ W,
            const float* __restrict__ bias, float* __restrict__ out) {
    constexpr int NJG = N / 8;
    constexpr int MG  = MT / 8;
    static_assert(MG * NJG == 256, "cfg");
    __shared__ __align__(16) float As[16 * MT];
    __shared__ __align__(16) float Ws[16 * N];

    const int t = threadIdx.x;
    const int jg = t % NJG, mg = t / NJG;
    const int m0 = blockIdx.x * MT;

    ull acc[8][4];
    #pragma unroll
    for (int a = 0; a < 8; a++)
        #pragma unroll
        for (int b = 0; b < 4; b++) acc[a][b] = 0ULL;

    for (int k0 = 0; k0 < K; k0 += 16) {
        for (int i = t; i < 16 * MT; i += 256)
            As[i] = A[(size_t)(k0 + i / MT) * NN + m0 + (i % MT)];
        for (int i = t; i < 16 * N; i += 256)
            Ws[i] = W[k0 * N + i];
        __syncthreads();
        #pragma unroll
        for (int kk = 0; kk < 16; kk++) {
            const float* ar = &As[kk * MT + mg];
            const ull* wr = (const ull*)&Ws[kk * N + jg * 8];
            ull w0 = wr[0], w1 = wr[1], w2 = wr[2], w3 = wr[3];
            #pragma unroll
            for (int tt = 0; tt < 8; tt++) {
                float a = ar[tt * MG];
                ull ab = pack2(a, a);
                ffma2(acc[tt][0], ab, w0);
                ffma2(acc[tt][1], ab, w1);
                ffma2(acc[tt][2], ab, w2);
                ffma2(acc[tt][3], ab, w3);
            }
        }
        __syncthreads();
    }

    #pragma unroll
    for (int tt = 0; tt < 8; tt++) {
        size_t node = m0 + mg + tt * MG;
        #pragma unroll
        for (int p = 0; p < 4; p++) {
            float x, y; unpack2(acc[tt][p], x, y);
            int j = jg * 8 + 2 * p;
            x = fmaxf(x + bias[j], 0.0f);
            y = fmaxf(y + bias[j + 1], 0.0f);
            *reinterpret_cast<float2*>(&out[node * N + j]) = make_float2(x, y);
        }
    }
}

// ---------------- pool + FC ----------------
__global__ void pool_fc_kernel(const float* __restrict__ h,
                               const float* __restrict__ fcW1, const float* __restrict__ fcb1,
                               const float* __restrict__ fcW2, const float* __restrict__ fcb2,
                               float* __restrict__ out) {
    __shared__ float red[256];
    __shared__ float pool[64];
    __shared__ float z1[10];
    int g = blockIdx.x, t = threadIdx.x;
    int f = t & 63, part = t >> 6;
    float s = 0.0f;
    for (int n = part; n < NPG; n += 4)
        s += h[(size_t)(g * NPG + n) * 64 + f];
    red[t] = s;
    __syncthreads();
    if (part == 0)
        pool[f] = (red[f] + red[64 + f] + red[128 + f] + red[192 + f]) * (1.0f / NPG);
    __syncthreads();
    if (t < 10) {
        float z = fcb1[t];
        for (int i = 0; i < 64; i++) z += pool[i] * fcW1[i * 10 + t];
        z1[t] = fmaxf(z, 0.0f);
    }
    __syncthreads();
    if (t < 10) {
        float z = fcb2[t];
        for (int j = 0; j < 10; j++) z += z1[j] * fcW2[j * 10 + t];
        out[g * 10 + t] = z;
    }
}

// ---------------- launch ----------------
extern "C" void kernel_launch(void* const* d_in, const int* in_sizes, int n_in,
                              void* d_out, int out_size) {
    const float* x     = (const float*)d_in[0];
    const int*   ei    = (const int*)d_in[1];
    const int*   batch = (const int*)d_in[2];
    const float* lam   = (const float*)d_in[3];
    const float* W1 = (const float*)d_in[4];  const float* b1 = (const float*)d_in[5];
    const float* W2 = (const float*)d_in[6];  const float* b2 = (const float*)d_in[7];
    const float* W3 = (const float*)d_in[8];  const float* b3 = (const float*)d_in[9];
    const float* fcW1 = (const float*)d_in[10]; const float* fcb1 = (const float*)d_in[11];
    const float* fcW2 = (const float*)d_in[12]; const float* fcb2 = (const float*)d_in[13];
    float* out = (float*)d_out;

    const int SMEM = 2 * NPG * PAD * sizeof(float);  // 139264
    cudaFuncSetAttribute(spmv_kernel<128>, cudaFuncAttributeMaxDynamicSharedMemorySize, SMEM);
    cudaFuncSetAttribute(spmv_kernel<32>,  cudaFuncAttributeMaxDynamicSharedMemorySize, SMEM);
    cudaFuncSetAttribute(spmv_kernel<64>,  cudaFuncAttributeMaxDynamicSharedMemorySize, SMEM);

    float* tx = nullptr; float* ha = nullptr; float* hb = nullptr;
    cudaGetSymbolAddress((void**)&tx, g_tx);
    cudaGetSymbolAddress((void**)&ha, g_ha);
    cudaGetSymbolAddress((void**)&hb, g_hb);

    zero_kernel<<<NN / 256, 256>>>();
    deg_kernel<<<NE / 256, 256>>>(ei);
    node_kernel<<<NN / 256, 256>>>(batch, lam);
    scan_kernel<<<1, 1024>>>();
    fill_kernel<<<NE / 256, 256>>>(ei, batch, lam);

    spmv_kernel<128><<<dim3(8, NG), 1024, SMEM>>>(x, tx);
    gemm_kernel<640, 32, 512><<<NN / 512, 256>>>(tx, W1, b1, ha);

    spmv_kernel<32><<<dim3(2, NG), 1024, SMEM>>>(ha, tx);
    gemm_kernel<160, 64, 256><<<NN / 256, 256>>>(tx, W2, b2, hb);

    spmv_kernel<64><<<dim3(4, NG), 1024, SMEM>>>(hb, tx);
    gemm_kernel<320, 64, 256><<<NN / 256, 256>>>(tx, W3, b3, ha);

    pool_fc_kernel<<<NG, 256>>>(ha, fcW1, fcb1, fcW2, fcb2, out);
}

// round 5
// speedup vs baseline: 1.0128x; 1.0128x over previous
#include <cuda_runtime.h>
#include <cuda_bf16.h>

#define NN      65536
#define NE      1048576
#define NG      64
#define NPG     1024
#define CF      16
#define PAD     17
#define ESTRIDE 20480   // per-graph edge region (mean 16384, sigma~127)

typedef unsigned long long ull;

__device__ int   g_deg[NN];
__device__ int   g_cnt[NN];
__device__ int   g_cur[NN];
__device__ int   g_rowstart[NN];
__device__ float g_dis[NN];
__device__ float g_diag[NN];
__device__ int2  g_edges[NG * ESTRIDE + 2];   // zero-initialized; pads stay 0
__device__ float g_tx[640ull * NN];
__device__ float g_ha[(size_t)NN * 64];
__device__ float g_hb[(size_t)NN * 64];

__device__ __forceinline__ ull pack2(float x, float y) {
    ull r; asm("mov.b64 %0, {%1, %2};" : "=l"(r) : "f"(x), "f"(y)); return r;
}
__device__ __forceinline__ void ffma2(ull& d, ull a, ull b) {
    asm("fma.rn.f32x2 %0, %1, %2, %0;" : "+l"(d) : "l"(a), "l"(b));
}
__device__ __forceinline__ void unpack2(ull v, float& x, float& y) {
    asm("mov.b64 {%0, %1}, %2;" : "=f"(x), "=f"(y) : "l"(v));
}

// ---------------- prep ----------------
__global__ void zero_kernel() {
    int i = blockIdx.x * blockDim.x + threadIdx.x;
    if (i < NN) { g_deg[i] = 0; g_cnt[i] = 0; g_cur[i] = 0; }
}

__global__ void deg_kernel(const int* __restrict__ ei) {
    int e = blockIdx.x * blockDim.x + threadIdx.x;
    if (e >= NE) return;
    int s = ei[e], d = ei[NE + e];
    if (s != d) { atomicAdd(&g_deg[s], 1); atomicAdd(&g_cnt[d], 1); }
}

__global__ void node_kernel(const int* __restrict__ batch,
                            const float* __restrict__ lam) {
    int n = blockIdx.x * blockDim.x + threadIdx.x;
    if (n >= NN) return;
    int dg = g_deg[n];
    g_dis[n]  = (dg > 0) ? rsqrtf((float)dg) : 0.0f;
    g_diag[n] = 2.0f / lam[batch[n]] - 1.0f;
}

// per-graph block scan: rowstart[n] = g*ESTRIDE + exclusive_prefix(round_up_even(cnt))
__global__ void __launch_bounds__(1024) scan2_kernel() {
    __shared__ int wsum[32];
    int g = blockIdx.x, t = threadIdx.x;
    int n = g * NPG + t;
    int c  = g_cnt[n];
    int rc = (c + 1) & ~1;
    int v = rc;
    #pragma unroll
    for (int o = 1; o < 32; o <<= 1) {
        int u = __shfl_up_sync(0xffffffffu, v, o);
        if ((t & 31) >= o) v += u;
    }
    if ((t & 31) == 31) wsum[t >> 5] = v;
    __syncthreads();
    if (t < 32) {
        int w = wsum[t];
        #pragma unroll
        for (int o = 1; o < 32; o <<= 1) {
            int u = __shfl_up_sync(0xffffffffu, w, o);
            if (t >= o) w += u;
        }
        wsum[t] = w;
    }
    __syncthreads();
    int excl = v - rc + ((t >= 32) ? wsum[(t >> 5) - 1] : 0);
    int rs = g * ESTRIDE + excl;
    g_rowstart[n] = rs;
    if (c & 1) g_edges[rs + c] = make_int2(0, 0);   // zero-weight pad slot
}

__global__ void fill_kernel(const int* __restrict__ ei,
                            const int* __restrict__ batch,
                            const float* __restrict__ lam) {
    int e = blockIdx.x * blockDim.x + threadIdx.x;
    if (e >= NE) return;
    int s = ei[e], d = ei[NE + e];
    if (s == d) return;
    float w = -2.0f * g_dis[s] * g_dis[d] / lam[batch[s]];
    int idx = g_rowstart[d] + atomicAdd(&g_cur[d], 1);
    g_edges[idx] = make_int2(s & (NPG - 1), __float_as_int(w));
}

// ---------------- Chebyshev recurrence (warp per node, 2 edges/iter) ----------------
template<int F>
__global__ void __launch_bounds__(1024, 1)
spmv_kernel(const float* __restrict__ hin, float* __restrict__ txout) {
    extern __shared__ float sm[];
    float* buf0 = sm;
    float* buf1 = sm + NPG * PAD;

    const int g = blockIdx.y, cb = blockIdx.x * CF, t = threadIdx.x;
    const int gbase = g * NPG;

    const float* hp = hin + (size_t)gbase * F + cb;
    #pragma unroll
    for (int r = 0; r < CF; r++) {
        int i = r * 1024 + t;
        buf0[(i >> 4) * PAD + (i & 15)] = hp[(i >> 4) * F + (i & 15)];
    }
    __syncthreads();

    #pragma unroll
    for (int f = 0; f < CF; f++)
        txout[(size_t)(cb + f) * NN + gbase + t] = buf0[t * PAD + f];

    const int lane = t & 31, warp = t >> 5;
    const int fl = lane & 15, eo = lane >> 4;   // eo: 0 = even edges, 1 = odd edges
    float* cur = buf0; float* oth = buf1;

    for (int k = 1; k < 5; k++) {
        #pragma unroll 1
        for (int p = 0; p < 32; p++) {
            int dloc = warp * 32 + p;
            int node = gbase + dloc;
            int rs   = g_rowstart[node];
            int deg  = g_cnt[node];
            int pairs = (deg + 1) >> 1;
            int base = rs + eo;
            float acc = 0.0f;
            int i = 0;
            for (; i + 2 <= pairs; i += 2) {
                int2 e0 = g_edges[base + 2 * i];
                int2 e1 = g_edges[base + 2 * i + 2];
                acc += __int_as_float(e0.y) * cur[e0.x * PAD + fl];
                acc += __int_as_float(e1.y) * cur[e1.x * PAD + fl];
            }
            if (i < pairs) {
                int2 e0 = g_edges[base + 2 * i];
                acc += __int_as_float(e0.y) * cur[e0.x * PAD + fl];
            }
            acc += __shfl_xor_sync(0xffffffffu, acc, 16);
            if (eo == 0) {
                int idx = dloc * PAD + fl;
                float lh = acc + g_diag[node] * cur[idx];
                oth[idx] = (k == 1) ? lh : 2.0f * lh - oth[idx];
            }
        }
        __syncthreads();
        #pragma unroll
        for (int f = 0; f < CF; f++)
            txout[(size_t)(k * F + cb + f) * NN + gbase + t] = oth[t * PAD + f];
        float* tmp = cur; cur = oth; oth = tmp;
        __syncthreads();
    }
}

// ---------------- GEMM: out = relu(A^T W + b), A:[K][NN], W:[K][N] ----------------
template<int K, int N, int MT>
__global__ void __launch_bounds__(256)
gemm_kernel(const float* __restrict__ A, const float* __restrict__ W,
            const float* __restrict__ bias, float* __restrict__ out) {
    constexpr int NJG = N / 8;
    constexpr int MG  = MT / 8;
    static_assert(MG * NJG == 256, "cfg");
    __shared__ __align__(16) float As[16 * MT];
    __shared__ __align__(16) float Ws[16 * N];

    const int t = threadIdx.x;
    const int jg = t % NJG, mg = t / NJG;
    const int m0 = blockIdx.x * MT;

    ull acc[8][4];
    #pragma unroll
    for (int a = 0; a < 8; a++)
        #pragma unroll
        for (int b = 0; b < 4; b++) acc[a][b] = 0ULL;

    for (int k0 = 0; k0 < K; k0 += 16) {
        for (int i = t; i < 16 * MT; i += 256)
            As[i] = A[(size_t)(k0 + i / MT) * NN + m0 + (i % MT)];
        for (int i = t; i < 16 * N; i += 256)
            Ws[i] = W[k0 * N + i];
        __syncthreads();
        #pragma unroll
        for (int kk = 0; kk < 16; kk++) {
            const float* ar = &As[kk * MT + mg];
            const ull* wr = (const ull*)&Ws[kk * N + jg * 8];
            ull w0 = wr[0], w1 = wr[1], w2 = wr[2], w3 = wr[3];
            #pragma unroll
            for (int tt = 0; tt < 8; tt++) {
                float a = ar[tt * MG];
                ull ab = pack2(a, a);
                ffma2(acc[tt][0], ab, w0);
                ffma2(acc[tt][1], ab, w1);
                ffma2(acc[tt][2], ab, w2);
                ffma2(acc[tt][3], ab, w3);
            }
        }
        __syncthreads();
    }

    #pragma unroll
    for (int tt = 0; tt < 8; tt++) {
        size_t node = m0 + mg + tt * MG;
        #pragma unroll
        for (int p = 0; p < 4; p++) {
            float x, y; unpack2(acc[tt][p], x, y);
            int j = jg * 8 + 2 * p;
            x = fmaxf(x + bias[j], 0.0f);
            y = fmaxf(y + bias[j + 1], 0.0f);
            *reinterpret_cast<float2*>(&out[node * N + j]) = make_float2(x, y);
        }
    }
}

// ---------------- pool + FC ----------------
__global__ void pool_fc_kernel(const float* __restrict__ h,
                               const float* __restrict__ fcW1, const float* __restrict__ fcb1,
                               const float* __restrict__ fcW2, const float* __restrict__ fcb2,
                               float* __restrict__ out) {
    __shared__ float red[256];
    __shared__ float pool[64];
    __shared__ float z1[10];
    int g = blockIdx.x, t = threadIdx.x;
    int f = t & 63, part = t >> 6;
    float s = 0.0f;
    for (int n = part; n < NPG; n += 4)
        s += h[(size_t)(g * NPG + n) * 64 + f];
    red[t] = s;
    __syncthreads();
    if (part == 0)
        pool[f] = (red[f] + red[64 + f] + red[128 + f] + red[192 + f]) * (1.0f / NPG);
    __syncthreads();
    if (t < 10) {
        float z = fcb1[t];
        for (int i = 0; i < 64; i++) z += pool[i] * fcW1[i * 10 + t];
        z1[t] = fmaxf(z, 0.0f);
    }
    __syncthreads();
    if (t < 10) {
        float z = fcb2[t];
        for (int j = 0; j < 10; j++) z += z1[j] * fcW2[j * 10 + t];
        out[g * 10 + t] = z;
    }
}

// ---------------- launch ----------------
extern "C" void kernel_launch(void* const* d_in, const int* in_sizes, int n_in,
                              void* d_out, int out_size) {
    const float* x     = (const float*)d_in[0];
    const int*   ei    = (const int*)d_in[1];
    const int*   batch = (const int*)d_in[2];
    const float* lam   = (const float*)d_in[3];
    const float* W1 = (const float*)d_in[4];  const float* b1 = (const float*)d_in[5];
    const float* W2 = (const float*)d_in[6];  const float* b2 = (const float*)d_in[7];
    const float* W3 = (const float*)d_in[8];  const float* b3 = (const float*)d_in[9];
    const float* fcW1 = (const float*)d_in[10]; const float* fcb1 = (const float*)d_in[11];
    const float* fcW2 = (const float*)d_in[12]; const float* fcb2 = (const float*)d_in[13];
    float* out = (float*)d_out;

    const int SMEM = 2 * NPG * PAD * sizeof(float);  // 139264
    cudaFuncSetAttribute(spmv_kernel<128>, cudaFuncAttributeMaxDynamicSharedMemorySize, SMEM);
    cudaFuncSetAttribute(spmv_kernel<32>,  cudaFuncAttributeMaxDynamicSharedMemorySize, SMEM);
    cudaFuncSetAttribute(spmv_kernel<64>,  cudaFuncAttributeMaxDynamicSharedMemorySize, SMEM);

    float* tx = nullptr; float* ha = nullptr; float* hb = nullptr;
    cudaGetSymbolAddress((void**)&tx, g_tx);
    cudaGetSymbolAddress((void**)&ha, g_ha);
    cudaGetSymbolAddress((void**)&hb, g_hb);

    zero_kernel<<<NN / 256, 256>>>();
    deg_kernel<<<NE / 256, 256>>>(ei);
    node_kernel<<<NN / 256, 256>>>(batch, lam);
    scan2_kernel<<<NG, 1024>>>();
    fill_kernel<<<NE / 256, 256>>>(ei, batch, lam);

    spmv_kernel<128><<<dim3(8, NG), 1024, SMEM>>>(x, tx);
    gemm_kernel<640, 32, 512><<<NN / 512, 256>>>(tx, W1, b1, ha);

    spmv_kernel<32><<<dim3(2, NG), 1024, SMEM>>>(ha, tx);
    gemm_kernel<160, 64, 256><<<NN / 256, 256>>>(tx, W2, b2, hb);

    spmv_kernel<64><<<dim3(4, NG), 1024, SMEM>>>(hb, tx);
    gemm_kernel<320, 64, 256><<<NN / 256, 256>>>(tx, W3, b3, ha);

    pool_fc_kernel<<<NG, 256>>>(ha, fcW1, fcb1, fcW2, fcb2, out);
}